// round 2
// baseline (speedup 1.0000x reference)
#include <cuda_runtime.h>
#include <math_constants.h>

// Problem constants (fixed by the dataset: B=8192, D=256, margin=0.3)
#define BB 8192
#define DD 256
#define TI 128      // rows per block tile
#define TJ 128      // cols per block tile
#define KB 16       // k-chunk
#define NSPLIT 4    // j-range splits (parallelism)
#define MARGIN_F 0.3f

// Scratch (no allocations allowed in kernel_launch)
__device__ float g_sq[BB];
__device__ float g_pmax[NSPLIT * BB];
__device__ float g_pmin[NSPLIT * BB];

// ---------------------------------------------------------------------------
// 1) Row squared norms: one warp per row, coalesced, shuffle reduce.
// ---------------------------------------------------------------------------
__global__ void sq_kernel(const float* __restrict__ x) {
    int row  = blockIdx.x * 8 + (threadIdx.x >> 5);
    int lane = threadIdx.x & 31;
    const float* p = x + (size_t)row * DD;
    float s = 0.f;
    #pragma unroll
    for (int k = lane; k < DD; k += 32) {
        float v = p[k];
        s = fmaf(v, v, s);
    }
    #pragma unroll
    for (int o = 16; o; o >>= 1) s += __shfl_down_sync(0xffffffffu, s, o);
    if (lane == 0) g_sq[row] = s;
}

// ---------------------------------------------------------------------------
// 2) Fused Gram-tile + hard mining.
//    Each block: 128 rows, one j-split (BB/NSPLIT columns).
//    Tracks per-row max over positives / min over negatives of (sq[j] - 2*dot);
//    the sq[i] term cancels in both the loss and the precision comparison.
// ---------------------------------------------------------------------------
__global__ void __launch_bounds__(256)
triplet_main(const float* __restrict__ x, const int* __restrict__ tgt) {
    __shared__ float As[KB][TI];
    __shared__ float Bs[KB][TJ];
    __shared__ float sSq[TJ];
    __shared__ int   sLbl[TJ];
    __shared__ float sRedMax[TI][17];   // padded to avoid bank conflicts
    __shared__ float sRedMin[TI][17];

    const int tid = threadIdx.x;
    const int tx  = tid & 15;
    const int ty  = tid >> 4;
    const int i0  = blockIdx.x * TI;
    const int spl = blockIdx.y;
    const int jbeg = spl * (BB / NSPLIT);
    const int jend = jbeg + (BB / NSPLIT);

    int lbli[8];
    #pragma unroll
    for (int r = 0; r < 8; r++) lbli[r] = tgt[i0 + ty * 8 + r];

    float maxp[8], minn[8];
    #pragma unroll
    for (int r = 0; r < 8; r++) { maxp[r] = -CUDART_INF_F; minn[r] = CUDART_INF_F; }

    for (int j0 = jbeg; j0 < jend; j0 += TJ) {
        if (tid < TJ) {
            sSq[tid]  = g_sq[j0 + tid];
            sLbl[tid] = tgt[j0 + tid];
        }

        float acc[8][8];
        #pragma unroll
        for (int r = 0; r < 8; r++)
            #pragma unroll
            for (int c = 0; c < 8; c++) acc[r][c] = 0.f;

        for (int kb = 0; kb < DD; kb += KB) {
            __syncthreads();
            // Load A tile & B tile: 128 rows x 16 k each, float4 vectorized.
            #pragma unroll
            for (int l = 0; l < 2; l++) {
                int idx = tid * 2 + l;          // 0..511
                int row = idx >> 2;             // 0..127
                int kq  = (idx & 3) * 4;        // 0,4,8,12
                float4 va = *(const float4*)(x + (size_t)(i0 + row) * DD + kb + kq);
                As[kq + 0][row] = va.x; As[kq + 1][row] = va.y;
                As[kq + 2][row] = va.z; As[kq + 3][row] = va.w;
                float4 vb = *(const float4*)(x + (size_t)(j0 + row) * DD + kb + kq);
                Bs[kq + 0][row] = vb.x; Bs[kq + 1][row] = vb.y;
                Bs[kq + 2][row] = vb.z; Bs[kq + 3][row] = vb.w;
            }
            __syncthreads();

            #pragma unroll
            for (int k = 0; k < KB; k++) {
                float a[8], b[8];
                #pragma unroll
                for (int r = 0; r < 8; r++) a[r] = As[k][ty * 8 + r];
                #pragma unroll
                for (int c = 0; c < 8; c++) b[c] = Bs[k][tx * 8 + c];
                #pragma unroll
                for (int r = 0; r < 8; r++)
                    #pragma unroll
                    for (int c = 0; c < 8; c++)
                        acc[r][c] = fmaf(a[r], b[c], acc[r][c]);
            }
        }

        // Consume this tile's dots against labels.  val = sq[j] - 2*dot.
        #pragma unroll
        for (int c = 0; c < 8; c++) {
            int j = tx * 8 + c;
            float sj = sSq[j];
            int   lj = sLbl[j];
            #pragma unroll
            for (int r = 0; r < 8; r++) {
                float val = fmaf(-2.f, acc[r][c], sj);
                if (lj == lbli[r]) maxp[r] = fmaxf(maxp[r], val);
                else               minn[r] = fminf(minn[r], val);
            }
        }
        __syncthreads();   // protect sSq/sLbl before next tile overwrites
    }

    // Reduce the 16 column-slices (tx) per row.
    #pragma unroll
    for (int r = 0; r < 8; r++) {
        sRedMax[ty * 8 + r][tx] = maxp[r];
        sRedMin[ty * 8 + r][tx] = minn[r];
    }
    __syncthreads();
    if (tid < TI) {
        float mp = -CUDART_INF_F, mn = CUDART_INF_F;
        #pragma unroll
        for (int t = 0; t < 16; t++) {
            mp = fmaxf(mp, sRedMax[tid][t]);
            mn = fminf(mn, sRedMin[tid][t]);
        }
        g_pmax[spl * BB + i0 + tid] = mp;
        g_pmin[spl * BB + i0 + tid] = mn;
    }
}

// ---------------------------------------------------------------------------
// 3) Combine splits, compute loss & precision. Single block -> deterministic.
// ---------------------------------------------------------------------------
__global__ void triplet_final(float* __restrict__ out) {
    __shared__ float sL[256];
    __shared__ float sP[256];
    int tid = threadIdx.x;
    float lsum = 0.f, pcnt = 0.f;
    for (int i = tid; i < BB; i += 256) {
        float mp = -CUDART_INF_F, mn = CUDART_INF_F;
        #pragma unroll
        for (int s = 0; s < NSPLIT; s++) {
            mp = fmaxf(mp, g_pmax[s * BB + i]);
            mn = fminf(mn, g_pmin[s * BB + i]);
        }
        float d = mp - mn + MARGIN_F;       // == dist_ap - dist_an + margin
        lsum += (d > 0.f) ? d : 0.f;
        pcnt += (mn > mp) ? 1.f : 0.f;      // dist_an > dist_ap
    }
    sL[tid] = lsum; sP[tid] = pcnt;
    __syncthreads();
    #pragma unroll
    for (int o = 128; o; o >>= 1) {
        if (tid < o) { sL[tid] += sL[tid + o]; sP[tid] += sP[tid + o]; }
        __syncthreads();
    }
    if (tid == 0) {
        out[0] = sL[0] / (float)BB;
        out[1] = sP[0] / (float)BB;
    }
}

extern "C" void kernel_launch(void* const* d_in, const int* in_sizes, int n_in,
                              void* d_out, int out_size) {
    const float* x = (const float*)d_in[0];
    const int*   t = (const int*)d_in[1];   // JAX x64-disabled: int64 request -> int32
    float*       o = (float*)d_out;

    sq_kernel<<<BB / 8, 256>>>(x);
    dim3 grid(BB / TI, NSPLIT);
    triplet_main<<<grid, 256>>>(x, t);
    triplet_final<<<1, 256>>>(o);
}